// round 2
// baseline (speedup 1.0000x reference)
#include <cuda_runtime.h>

#define NGRID 10000
#define NSTEP 365
#define NMUL 16
#define NEARZERO 1e-5f

__global__ __launch_bounds__(256, 4)
void hbv_waterloss_kernel(
    const float* __restrict__ x,     // (365, 10000, 3) P,T,PET
    const float* __restrict__ praw,  // (365, 10000, 3, 16) -- only step 364 used
    const float* __restrict__ wraw,  // (10000, 13, 16)
    const float* __restrict__ ac,    // (10000,)
    float* __restrict__ out)         // (365, 10000)
{
    const int tid = blockIdx.x * blockDim.x + threadIdx.x;
    const int g = tid >> 4;        // grid cell
    const int m = tid & 15;        // multiplier index within grid
    if (g >= NGRID) return;

    // ---- parameter scaling (HBV params from last timestep: static_idx = -1) ----
    const float* pr = praw + ((size_t)364 * NGRID + g) * (3 * NMUL) + m;  // stride 16 per param idx
    const float parBETA   = 1.0f  + pr[0]      * 5.0f;    // (1, 6)
    const float parK0     = 0.05f + pr[16]     * 0.85f;   // (0.05, 0.9)
    const float parBETAET = 0.3f  + pr[32]     * 4.7f;    // (0.3, 5)

    const float* wr = wraw + (size_t)g * (13 * NMUL) + m;
    const float parFC    = 50.0f  + wr[0]   * 950.0f;   // (50, 1000)
    const float parK1    = 0.01f  + wr[16]  * 0.49f;    // (0.01, 0.5)
    const float parK2    = 0.001f + wr[32]  * 0.199f;   // (0.001, 0.2)
    const float parLP    = 0.2f   + wr[48]  * 0.8f;     // (0.2, 1)
    const float parPERC  =          wr[64]  * 10.0f;    // (0, 10)
    const float parUZL   =          wr[80]  * 100.0f;   // (0, 100)
    const float parTT    = -2.5f  + wr[96]  * 5.0f;     // (-2.5, 2.5)
    const float parCFMAX = 0.5f   + wr[112] * 9.5f;     // (0.5, 10)
    const float parCFR   =          wr[128] * 0.1f;     // (0, 0.1)
    const float parCWH   =          wr[144] * 0.2f;     // (0, 0.2)
    const float parC     =          wr[160];            // (0, 1)
    const float parTR    =          wr[176] * 20.0f;    // (0, 20)
    const float parAc    =          wr[192] * 2500.0f;  // (0, 2500)

    // ---- regional flow (time-invariant per (g,m)) ----
    const float acm = ac[g];
    float regional_flow;
    {
        const float rf = fminf(fmaxf((acm - parAc) * 0.001f, -1.0f), 1.0f);
        if (acm < 2500.0f) {
            regional_flow = rf * parTR;
        } else {
            const float e = fminf(fmaxf(-(acm - 2500.0f) * (1.0f / 50.0f), -10.0f), 0.0f);
            regional_flow = expf(e) * parTR;
        }
    }

    const float invFC    = 1.0f / parFC;
    const float invLPFC  = 1.0f / (parLP * parFC);
    const float CFRCFMAX = parCFR * parCFMAX;

    float SNOWPACK = 0.001f, MELTWATER = 0.001f, SM = 0.001f, SUZ = 0.001f, SLZ = 0.001f;

    const float* xg = x + (size_t)g * 3;

    #pragma unroll 1
    for (int t = 0; t < NSTEP; ++t) {
        const float* xt = xg + (size_t)t * (NGRID * 3);
        const float Pm   = __ldg(xt + 0);
        const float Tm   = __ldg(xt + 1);
        const float PETm = __ldg(xt + 2);

        // snow routine
        const bool warm = (Tm >= parTT);
        const float RAIN = warm ? Pm : 0.0f;
        const float SNOW = warm ? 0.0f : Pm;
        SNOWPACK += SNOW;
        const float melt = fminf(fmaxf(parCFMAX * (Tm - parTT), 0.0f), SNOWPACK);
        MELTWATER += melt;
        SNOWPACK  -= melt;
        const float refreezing = fminf(fmaxf(CFRCFMAX * (parTT - Tm), 0.0f), MELTWATER);
        SNOWPACK  += refreezing;
        MELTWATER -= refreezing;
        const float tosoil = fmaxf(MELTWATER - parCWH * SNOWPACK, 0.0f);
        MELTWATER -= tosoil;

        // soil routine
        const float soil_wetness = fminf(fmaxf(__powf(SM * invFC, parBETA), 0.0f), 1.0f);
        const float rt = RAIN + tosoil;
        const float recharge = rt * soil_wetness;
        SM += rt - recharge;
        const float excess = fmaxf(SM - parFC, 0.0f);
        SM -= excess;
        const float evapfactor = fminf(fmaxf(__powf(SM * invLPFC, parBETAET), 0.0f), 1.0f);
        const float ETact = fminf(SM, PETm * evapfactor);
        SM = fmaxf(SM - ETact, NEARZERO);
        const float capillary = fminf(SLZ, parC * SLZ * (1.0f - fminf(SM * invFC, 1.0f)));
        SM  = fmaxf(SM + capillary, NEARZERO);
        SLZ = fmaxf(SLZ - capillary, NEARZERO);

        // response routine
        SUZ += recharge + excess;
        const float PERC = fminf(SUZ, parPERC);
        SUZ -= PERC;
        const float Q0 = parK0 * fmaxf(SUZ - parUZL, 0.0f);
        SUZ -= Q0;
        const float Q1 = parK1 * SUZ;
        SUZ -= Q1;
        SLZ += PERC;
        SLZ = fmaxf(SLZ + regional_flow, 0.0f);
        const float Q2 = parK2 * SLZ;
        SLZ -= Q2;

        // mean over the 16 muls of this grid (lanes [0..15] / [16..31] are two groups)
        float q = Q0 + Q1 + Q2;
        q += __shfl_xor_sync(0xffffffffu, q, 8);
        q += __shfl_xor_sync(0xffffffffu, q, 4);
        q += __shfl_xor_sync(0xffffffffu, q, 2);
        q += __shfl_xor_sync(0xffffffffu, q, 1);
        if (m == 0) out[(size_t)t * NGRID + g] = q * (1.0f / 16.0f);
    }
}

extern "C" void kernel_launch(void* const* d_in, const int* in_sizes, int n_in,
                              void* d_out, int out_size) {
    const float* x  = nullptr;   // 365*10000*3      = 10,950,000
    const float* pr = nullptr;   // 365*10000*3*16   = 175,200,000
    const float* wr = nullptr;   // 10000*13*16      = 2,080,000
    const float* ac = nullptr;   // 10000
    for (int i = 0; i < n_in; ++i) {
        const long n = (long)in_sizes[i];
        if      (n == 365L * NGRID * 3)            x  = (const float*)d_in[i];
        else if (n == 365L * NGRID * 3 * NMUL)     pr = (const float*)d_in[i];
        else if (n == (long)NGRID * 13 * NMUL)     wr = (const float*)d_in[i];
        else if (n == (long)NGRID)                 ac = (const float*)d_in[i];
    }
    const int threads = 256;
    const int blocks  = (NGRID * NMUL + threads - 1) / threads;  // 625
    hbv_waterloss_kernel<<<blocks, threads>>>(x, pr, wr, ac, (float*)d_out);
}

// round 3
// speedup vs baseline: 1.2257x; 1.2257x over previous
#include <cuda_runtime.h>

#define NGRID 10000
#define NSTEP 365
#define NMUL 16
#define NEARZERO 1e-5f
#define TBATCH 5            // 365 = 5 * 73, no remainder

__global__ __launch_bounds__(128)
void hbv_waterloss_kernel(
    const float* __restrict__ x,     // (365, 10000, 3) P,T,PET
    const float* __restrict__ praw,  // (365, 10000, 3, 16) -- only step 364 used
    const float* __restrict__ wraw,  // (10000, 13, 16)
    const float* __restrict__ ac,    // (10000,)
    float* __restrict__ out)         // (365, 10000)
{
    const int tid = blockIdx.x * blockDim.x + threadIdx.x;
    const int g = tid >> 4;        // grid cell
    const int m = tid & 15;        // multiplier index within grid
    if (g >= NGRID) return;

    // ---- parameter scaling (HBV params from last timestep: static_idx = -1) ----
    const float* pr = praw + ((size_t)364 * NGRID + g) * (3 * NMUL) + m;
    const float parBETA   = 1.0f  + pr[0]      * 5.0f;
    const float parK0     = 0.05f + pr[16]     * 0.85f;
    const float parBETAET = 0.3f  + pr[32]     * 4.7f;

    const float* wr = wraw + (size_t)g * (13 * NMUL) + m;
    const float parFC    = 50.0f  + wr[0]   * 950.0f;
    const float parK1    = 0.01f  + wr[16]  * 0.49f;
    const float parK2    = 0.001f + wr[32]  * 0.199f;
    const float parLP    = 0.2f   + wr[48]  * 0.8f;
    const float parPERC  =          wr[64]  * 10.0f;
    const float parUZL   =          wr[80]  * 100.0f;
    const float parTT    = -2.5f  + wr[96]  * 5.0f;
    const float parCFMAX = 0.5f   + wr[112] * 9.5f;
    const float parCFR   =          wr[128] * 0.1f;
    const float parCWH   =          wr[144] * 0.2f;
    const float parC     =          wr[160];
    const float parTR    =          wr[176] * 20.0f;
    const float parAc    =          wr[192] * 2500.0f;

    // ---- regional flow (time-invariant per (g,m)) ----
    const float acm = ac[g];
    float regional_flow;
    {
        const float rf = fminf(fmaxf((acm - parAc) * 0.001f, -1.0f), 1.0f);
        if (acm < 2500.0f) {
            regional_flow = rf * parTR;
        } else {
            const float e = fminf(fmaxf(-(acm - 2500.0f) * (1.0f / 50.0f), -10.0f), 0.0f);
            regional_flow = expf(e) * parTR;
        }
    }

    const float invFC    = 1.0f / parFC;
    const float invLPFC  = 1.0f / (parLP * parFC);
    const float CFRCFMAX = parCFR * parCFMAX;

    float SNOWPACK = 0.001f, MELTWATER = 0.001f, SM = 0.001f, SUZ = 0.001f, SLZ = 0.001f;

    const float* xt = x + (size_t)g * 3;           // advances NGRID*3 per step
    float* og = out + g;                            // advances NGRID per step

    #pragma unroll 1
    for (int tb = 0; tb < NSTEP / TBATCH; ++tb) {
        float qbuf[TBATCH];

        #pragma unroll
        for (int k = 0; k < TBATCH; ++k) {
            const float Pm   = __ldg(xt + 0);
            const float Tm   = __ldg(xt + 1);
            const float PETm = __ldg(xt + 2);
            xt += NGRID * 3;

            // snow routine
            const float dtt  = Tm - parTT;
            const float RAIN = (dtt >= 0.0f) ? Pm : 0.0f;
            const float SNOW = Pm - RAIN;
            SNOWPACK += SNOW;
            const float melt = fminf(fmaxf(parCFMAX * dtt, 0.0f), SNOWPACK);
            MELTWATER += melt;
            SNOWPACK  -= melt;
            const float refreezing = fminf(fmaxf(-CFRCFMAX * dtt, 0.0f), MELTWATER);
            SNOWPACK  += refreezing;
            MELTWATER -= refreezing;
            const float tosoil = fmaxf(MELTWATER - parCWH * SNOWPACK, 0.0f);
            MELTWATER -= tosoil;

            // soil routine (powf of positive base is >= 0 -> the max(.,0) of the clip is dead)
            const float soil_wetness = fminf(__powf(SM * invFC, parBETA), 1.0f);
            const float rt = RAIN + tosoil;
            const float recharge = rt * soil_wetness;
            SM += rt - recharge;
            const float excess = fmaxf(SM - parFC, 0.0f);
            SM -= excess;
            const float evapfactor = fminf(__powf(SM * invLPFC, parBETAET), 1.0f);
            const float ETact = fminf(SM, PETm * evapfactor);
            SM = fmaxf(SM - ETact, NEARZERO);
            const float capillary = fminf(SLZ, parC * SLZ * (1.0f - fminf(SM * invFC, 1.0f)));
            SM  = fmaxf(SM + capillary, NEARZERO);
            SLZ = fmaxf(SLZ - capillary, NEARZERO);

            // response routine
            SUZ += recharge + excess;
            const float PERC = fminf(SUZ, parPERC);
            SUZ -= PERC;
            const float Q0 = parK0 * fmaxf(SUZ - parUZL, 0.0f);
            SUZ -= Q0;
            const float Q1 = parK1 * SUZ;
            SUZ -= Q1;
            SLZ += PERC;
            SLZ = fmaxf(SLZ + regional_flow, 0.0f);
            const float Q2 = parK2 * SLZ;
            SLZ -= Q2;

            qbuf[k] = Q0 + Q1 + Q2;
        }

        // 5 independent 16-lane butterfly reductions -> shuffle latency pipelines
        #pragma unroll
        for (int k = 0; k < TBATCH; ++k) {
            float q = qbuf[k];
            q += __shfl_xor_sync(0xffffffffu, q, 8);
            q += __shfl_xor_sync(0xffffffffu, q, 4);
            q += __shfl_xor_sync(0xffffffffu, q, 2);
            q += __shfl_xor_sync(0xffffffffu, q, 1);
            qbuf[k] = q;
        }

        if (m == 0) {
            #pragma unroll
            for (int k = 0; k < TBATCH; ++k)
                og[(size_t)k * NGRID] = qbuf[k] * (1.0f / 16.0f);
        }
        og += (size_t)TBATCH * NGRID;
    }
}

extern "C" void kernel_launch(void* const* d_in, const int* in_sizes, int n_in,
                              void* d_out, int out_size) {
    const float* x  = nullptr;
    const float* pr = nullptr;
    const float* wr = nullptr;
    const float* ac = nullptr;
    for (int i = 0; i < n_in; ++i) {
        const long n = (long)in_sizes[i];
        if      (n == 365L * NGRID * 3)            x  = (const float*)d_in[i];
        else if (n == 365L * NGRID * 3 * NMUL)     pr = (const float*)d_in[i];
        else if (n == (long)NGRID * 13 * NMUL)     wr = (const float*)d_in[i];
        else if (n == (long)NGRID)                 ac = (const float*)d_in[i];
    }
    const int threads = 128;
    const int blocks  = (NGRID * NMUL + threads - 1) / threads;  // 1250
    hbv_waterloss_kernel<<<blocks, threads>>>(x, pr, wr, ac, (float*)d_out);
}

// round 4
// speedup vs baseline: 1.2390x; 1.0108x over previous
#include <cuda_runtime.h>

#define NGRID 10000
#define NSTEP 365
#define NMUL 16
#define NEARZERO 1e-5f
#define TBATCH 5            // 365 = 5 * 73, no remainder

__global__ __launch_bounds__(64)
void hbv_waterloss_kernel(
    const float* __restrict__ x,     // (365, 10000, 3) P,T,PET
    const float* __restrict__ praw,  // (365, 10000, 3, 16) -- only step 364 used
    const float* __restrict__ wraw,  // (10000, 13, 16)
    const float* __restrict__ ac,    // (10000,)
    float* __restrict__ out)         // (365, 10000)
{
    const int tid = blockIdx.x * blockDim.x + threadIdx.x;
    const int g = tid >> 3;        // grid cell
    const int m = tid & 7;         // this thread handles muls m and m+8
    if (g >= NGRID) return;

    // ---- parameter scaling (HBV params from last timestep: static_idx = -1) ----
    float parBETA[2], parK0[2], parBETAET[2];
    float parFC[2], parK1[2], parK2[2], parLP[2], parPERC[2], parUZL[2];
    float parTT[2], parCFMAX[2], parCWH[2], parC[2];
    float regional_flow[2], invFC[2], invLPFC[2], CFRCFMAX[2];

    const float acm = ac[g];

    #pragma unroll
    for (int j = 0; j < 2; ++j) {
        const int mm = m + j * 8;
        const float* pr = praw + ((size_t)364 * NGRID + g) * (3 * NMUL) + mm;
        parBETA[j]   = 1.0f  + pr[0]  * 5.0f;
        parK0[j]     = 0.05f + pr[16] * 0.85f;
        parBETAET[j] = 0.3f  + pr[32] * 4.7f;

        const float* wr = wraw + (size_t)g * (13 * NMUL) + mm;
        parFC[j]    = 50.0f  + wr[0]   * 950.0f;
        parK1[j]    = 0.01f  + wr[16]  * 0.49f;
        parK2[j]    = 0.001f + wr[32]  * 0.199f;
        parLP[j]    = 0.2f   + wr[48]  * 0.8f;
        parPERC[j]  =          wr[64]  * 10.0f;
        parUZL[j]   =          wr[80]  * 100.0f;
        parTT[j]    = -2.5f  + wr[96]  * 5.0f;
        parCFMAX[j] = 0.5f   + wr[112] * 9.5f;
        const float parCFR = wr[128] * 0.1f;
        parCWH[j]   =          wr[144] * 0.2f;
        parC[j]     =          wr[160];
        const float parTR  = wr[176] * 20.0f;
        const float parAc  = wr[192] * 2500.0f;

        // regional flow (time-invariant)
        const float rf = fminf(fmaxf((acm - parAc) * 0.001f, -1.0f), 1.0f);
        if (acm < 2500.0f) {
            regional_flow[j] = rf * parTR;
        } else {
            const float e = fminf(fmaxf(-(acm - 2500.0f) * (1.0f / 50.0f), -10.0f), 0.0f);
            regional_flow[j] = expf(e) * parTR;
        }

        invFC[j]    = 1.0f / parFC[j];
        invLPFC[j]  = 1.0f / (parLP[j] * parFC[j]);
        CFRCFMAX[j] = parCFR * parCFMAX[j];
    }

    float SNOWPACK[2]  = {0.001f, 0.001f};
    float MELTWATER[2] = {0.001f, 0.001f};
    float SM[2]        = {0.001f, 0.001f};
    float SUZ[2]       = {0.001f, 0.001f};
    float SLZ[2]       = {0.001f, 0.001f};

    const float* xt = x + (size_t)g * 3;
    float* og = out + g;

    #pragma unroll 1
    for (int tb = 0; tb < NSTEP / TBATCH; ++tb) {
        float qbuf[TBATCH];

        #pragma unroll
        for (int k = 0; k < TBATCH; ++k) {
            const float Pm   = __ldg(xt + 0);
            const float Tm   = __ldg(xt + 1);
            const float PETm = __ldg(xt + 2);
            xt += NGRID * 3;

            float qsum = 0.0f;
            #pragma unroll
            for (int j = 0; j < 2; ++j) {
                // snow routine
                const float dtt  = Tm - parTT[j];
                const float RAIN = (dtt >= 0.0f) ? Pm : 0.0f;
                const float SNOW = Pm - RAIN;
                SNOWPACK[j] += SNOW;
                const float melt = fminf(fmaxf(parCFMAX[j] * dtt, 0.0f), SNOWPACK[j]);
                MELTWATER[j] += melt;
                SNOWPACK[j]  -= melt;
                const float refreezing = fminf(fmaxf(-CFRCFMAX[j] * dtt, 0.0f), MELTWATER[j]);
                SNOWPACK[j]  += refreezing;
                MELTWATER[j] -= refreezing;
                const float tosoil = fmaxf(MELTWATER[j] - parCWH[j] * SNOWPACK[j], 0.0f);
                MELTWATER[j] -= tosoil;

                // soil routine (powf of positive base >= 0 -> lower clip is dead)
                const float soil_wetness = fminf(__powf(SM[j] * invFC[j], parBETA[j]), 1.0f);
                const float rt = RAIN + tosoil;
                const float recharge = rt * soil_wetness;
                SM[j] += rt - recharge;
                const float excess = fmaxf(SM[j] - parFC[j], 0.0f);
                SM[j] -= excess;
                const float evapfactor = fminf(__powf(SM[j] * invLPFC[j], parBETAET[j]), 1.0f);
                const float ETact = fminf(SM[j], PETm * evapfactor);
                SM[j] = fmaxf(SM[j] - ETact, NEARZERO);
                const float capillary = fminf(SLZ[j],
                    parC[j] * SLZ[j] * (1.0f - fminf(SM[j] * invFC[j], 1.0f)));
                SM[j]  = fmaxf(SM[j] + capillary, NEARZERO);
                SLZ[j] = fmaxf(SLZ[j] - capillary, NEARZERO);

                // response routine
                SUZ[j] += recharge + excess;
                const float PERC = fminf(SUZ[j], parPERC[j]);
                SUZ[j] -= PERC;
                const float Q0 = parK0[j] * fmaxf(SUZ[j] - parUZL[j], 0.0f);
                SUZ[j] -= Q0;
                const float Q1 = parK1[j] * SUZ[j];
                SUZ[j] -= Q1;
                SLZ[j] += PERC;
                SLZ[j] = fmaxf(SLZ[j] + regional_flow[j], 0.0f);
                const float Q2 = parK2[j] * SLZ[j];
                SLZ[j] -= Q2;

                qsum += Q0 + Q1 + Q2;
            }
            qbuf[k] = qsum;
        }

        // 5 independent 8-lane butterfly reductions -> shuffle latency pipelines
        #pragma unroll
        for (int k = 0; k < TBATCH; ++k) {
            float q = qbuf[k];
            q += __shfl_xor_sync(0xffffffffu, q, 4);
            q += __shfl_xor_sync(0xffffffffu, q, 2);
            q += __shfl_xor_sync(0xffffffffu, q, 1);
            qbuf[k] = q;
        }

        if (m == 0) {
            #pragma unroll
            for (int k = 0; k < TBATCH; ++k)
                og[(size_t)k * NGRID] = qbuf[k] * (1.0f / 16.0f);
        }
        og += (size_t)TBATCH * NGRID;
    }
}

extern "C" void kernel_launch(void* const* d_in, const int* in_sizes, int n_in,
                              void* d_out, int out_size) {
    const float* x  = nullptr;
    const float* pr = nullptr;
    const float* wr = nullptr;
    const float* ac = nullptr;
    for (int i = 0; i < n_in; ++i) {
        const long n = (long)in_sizes[i];
        if      (n == 365L * NGRID * 3)            x  = (const float*)d_in[i];
        else if (n == 365L * NGRID * 3 * NMUL)     pr = (const float*)d_in[i];
        else if (n == (long)NGRID * 13 * NMUL)     wr = (const float*)d_in[i];
        else if (n == (long)NGRID)                 ac = (const float*)d_in[i];
    }
    const int threads = 64;
    const int blocks  = (NGRID * (NMUL / 2) + threads - 1) / threads;  // 1250
    hbv_waterloss_kernel<<<blocks, threads>>>(x, pr, wr, ac, (float*)d_out);
}

// round 5
// speedup vs baseline: 1.3092x; 1.0567x over previous
#include <cuda_runtime.h>

#define NGRID 10000
#define NSTEP 365
#define NMUL 16
#define NEARZERO 1e-5f
#define TBATCH 5            // 365 = 5 * 73, no remainder

__global__ __launch_bounds__(32)
void hbv_waterloss_kernel(
    const float* __restrict__ x,     // (365, 10000, 3) P,T,PET
    const float* __restrict__ praw,  // (365, 10000, 3, 16) -- only step 364 used
    const float* __restrict__ wraw,  // (10000, 13, 16)
    const float* __restrict__ ac,    // (10000,)
    float* __restrict__ out)         // (365, 10000)
{
    const int tid = blockIdx.x * blockDim.x + threadIdx.x;
    const int g = tid >> 4;        // grid cell
    const int m = tid & 15;        // multiplier index within grid
    if (g >= NGRID) return;

    // ---- parameter scaling (HBV params from last timestep: static_idx = -1) ----
    const float* pr = praw + ((size_t)364 * NGRID + g) * (3 * NMUL) + m;
    const float parBETA   = 1.0f  + pr[0]      * 5.0f;
    const float parK0     = 0.05f + pr[16]     * 0.85f;
    const float parBETAET = 0.3f  + pr[32]     * 4.7f;

    const float* wr = wraw + (size_t)g * (13 * NMUL) + m;
    const float parFC    = 50.0f  + wr[0]   * 950.0f;
    const float parK1    = 0.01f  + wr[16]  * 0.49f;
    const float parK2    = 0.001f + wr[32]  * 0.199f;
    const float parLP    = 0.2f   + wr[48]  * 0.8f;
    const float parPERC  =          wr[64]  * 10.0f;
    const float parUZL   =          wr[80]  * 100.0f;
    const float parTT    = -2.5f  + wr[96]  * 5.0f;
    const float parCFMAX = 0.5f   + wr[112] * 9.5f;
    const float parCFR   =          wr[128] * 0.1f;
    const float parCWH   =          wr[144] * 0.2f;
    const float parC     =          wr[160];
    const float parTR    =          wr[176] * 20.0f;
    const float parAc    =          wr[192] * 2500.0f;

    // ---- regional flow (time-invariant per (g,m)) ----
    const float acm = ac[g];
    float regional_flow;
    {
        const float rf = fminf(fmaxf((acm - parAc) * 0.001f, -1.0f), 1.0f);
        if (acm < 2500.0f) {
            regional_flow = rf * parTR;
        } else {
            const float e = fminf(fmaxf(-(acm - 2500.0f) * (1.0f / 50.0f), -10.0f), 0.0f);
            regional_flow = expf(e) * parTR;
        }
    }

    const float invFC     = 1.0f / parFC;
    const float invLPFC   = 1.0f / (parLP * parFC);
    const float negCFRCFMAX = -(parCFR * parCFMAX);
    const float oneMK1    = 1.0f - parK1;   // SUZ after Q1 = SUZ*(1-K1)
    const float oneMK2    = 1.0f - parK2;   // SLZ after Q2 = SLZ*(1-K2)

    float SNOWPACK = 0.001f, MELTWATER = 0.001f, SM = 0.001f, SUZ = 0.001f, SLZ = 0.001f;

    const float* xt = x + (size_t)g * 3;    // advances NGRID*3 per step
    float* og = out + g;                    // advances NGRID per step

    #pragma unroll 1
    for (int tb = 0; tb < NSTEP / TBATCH; ++tb) {
        float qbuf[TBATCH];

        #pragma unroll
        for (int k = 0; k < TBATCH; ++k) {
            const float Pm   = __ldg(xt + 0);
            const float Tm   = __ldg(xt + 1);
            const float PETm = __ldg(xt + 2);
            xt += NGRID * 3;

            // ---- snow routine ----
            const float dtt  = Tm - parTT;
            const float RAIN = (dtt >= 0.0f) ? Pm : 0.0f;
            SNOWPACK += Pm - RAIN;
            const float melt = fminf(fmaxf(parCFMAX * dtt, 0.0f), SNOWPACK);
            MELTWATER += melt;
            SNOWPACK  -= melt;
            const float refreezing = fminf(fmaxf(negCFRCFMAX * dtt, 0.0f), MELTWATER);
            SNOWPACK  += refreezing;
            MELTWATER -= refreezing;
            const float tosoil = fmaxf(MELTWATER - parCWH * SNOWPACK, 0.0f);
            MELTWATER -= tosoil;

            // ---- soil routine ----
            // powf of non-negative base is >= 0 -> lower clip of jnp.clip is dead
            const float soil_wetness = fminf(__powf(SM * invFC, parBETA), 1.0f);
            const float rt = RAIN + tosoil;
            const float recharge = rt * soil_wetness;
            SM += rt - recharge;
            const float excess = fmaxf(SM - parFC, 0.0f);
            SM -= excess;
            const float evapfactor = fminf(__powf(SM * invLPFC, parBETAET), 1.0f);
            // ETact fold: max(SM - min(SM, PET*ef), NZ) == max(SM - PET*ef, NZ)
            SM = fmaxf(SM - PETm * evapfactor, NEARZERO);
            // capillary: parC<=1 and (1-min(SM/FC,1))<=1 -> product <= SLZ, outer min dead
            const float capillary = (parC * SLZ) * (1.0f - fminf(SM * invFC, 1.0f));
            SM  = fmaxf(SM + capillary, NEARZERO);
            SLZ = fmaxf(SLZ - capillary, NEARZERO);

            // ---- response routine ----
            SUZ += recharge + excess;
            const float PERC = fminf(SUZ, parPERC);
            SUZ -= PERC;
            const float Q0 = parK0 * fmaxf(SUZ - parUZL, 0.0f);
            SUZ -= Q0;
            const float Q1 = parK1 * SUZ;
            SUZ *= oneMK1;                       // == SUZ - Q1
            SLZ = fmaxf(SLZ + PERC + regional_flow, 0.0f);
            const float Q2 = parK2 * SLZ;
            SLZ *= oneMK2;                       // == SLZ - Q2
            qbuf[k] = Q0 + Q1 + Q2;
        }

        // 5 independent 16-lane butterfly reductions -> shuffle latency pipelines
        #pragma unroll
        for (int k = 0; k < TBATCH; ++k) {
            float q = qbuf[k];
            q += __shfl_xor_sync(0xffffffffu, q, 8);
            q += __shfl_xor_sync(0xffffffffu, q, 4);
            q += __shfl_xor_sync(0xffffffffu, q, 2);
            q += __shfl_xor_sync(0xffffffffu, q, 1);
            qbuf[k] = q;
        }

        if (m == 0) {
            #pragma unroll
            for (int k = 0; k < TBATCH; ++k)
                og[(size_t)k * NGRID] = qbuf[k] * (1.0f / 16.0f);
        }
        og += (size_t)TBATCH * NGRID;
    }
}

extern "C" void kernel_launch(void* const* d_in, const int* in_sizes, int n_in,
                              void* d_out, int out_size) {
    const float* x  = nullptr;
    const float* pr = nullptr;
    const float* wr = nullptr;
    const float* ac = nullptr;
    for (int i = 0; i < n_in; ++i) {
        const long n = (long)in_sizes[i];
        if      (n == 365L * NGRID * 3)            x  = (const float*)d_in[i];
        else if (n == 365L * NGRID * 3 * NMUL)     pr = (const float*)d_in[i];
        else if (n == (long)NGRID * 13 * NMUL)     wr = (const float*)d_in[i];
        else if (n == (long)NGRID)                 ac = (const float*)d_in[i];
    }
    // one warp per block: 5000 blocks -> 33/34 warps per SM, single wave,
    // near-perfect static balance across 148 SMs
    const int threads = 32;
    const int blocks  = (NGRID * NMUL + threads - 1) / threads;  // 5000
    hbv_waterloss_kernel<<<blocks, threads>>>(x, pr, wr, ac, (float*)d_out);
}